// round 8
// baseline (speedup 1.0000x reference)
#include <cuda_runtime.h>
#include <cuda_fp16.h>
#include <cuda_bf16.h>
#include <math.h>
#include <stdint.h>

#define N_SRC 100000
#define N_DST 50000
#define D_IN  128
#define D_OUT 64
#define BUCKET 128

#define TILES_Y 1563           // ceil(100000/64)
#define TILES_Z 782            // ceil(50000/64)

// ---------------- scratch (device globals; no allocations allowed) ---------
__device__ __half g_yh[(size_t)N_SRC * D_OUT];     // fp16(x @ W_l)   12.8 MB
__device__ float  g_z[(size_t)N_DST * D_OUT];      // x[:N_DST]@W_r   12.8 MB
__device__ int    g_cnt[N_DST];
__device__ int    g_src[(size_t)N_DST * BUCKET];   // bucketed CSR    25.6 MB
// W^T split into bf16 hi/lo, [n][k] row-major
__device__ __nv_bfloat16 g_wt1l[64 * 128], g_wt2l[64 * 128];
__device__ __nv_bfloat16 g_wt1r[64 * 128], g_wt2r[64 * 128];

__device__ __forceinline__ uint32_t smem_u32(const void* p) {
    uint32_t a;
    asm("{ .reg .u64 t; cvta.to.shared.u64 t, %1; cvt.u32.u64 %0, t; }"
        : "=r"(a) : "l"(p));
    return a;
}

// pack two f32 -> bf16x2 (lo = a, hi = b), single instruction
__device__ __forceinline__ uint32_t cvt_bf16x2(float a, float b) {
    uint32_t r;
    asm("cvt.rn.bf16x2.f32 %0, %1, %2;" : "=r"(r) : "f"(b), "f"(a));
    return r;
}

// ---------------------------------------------------------------------------
// zero counters + W^T bf16 hi/lo split (wt[n][k] = W[k][n]) in one launch
__global__ void prep_kernel(const float* __restrict__ Wl,
                            const float* __restrict__ Wr) {
    int i = blockIdx.x * blockDim.x + threadIdx.x;
    if (i < N_DST) g_cnt[i] = 0;
    if (i < 64 * 128) {
        int n = i & 63, k = i >> 6;
        float vl = Wl[k * 64 + n];
        __nv_bfloat16 h = __float2bfloat16(vl);
        g_wt1l[n * 128 + k] = h;
        g_wt2l[n * 128 + k] = __float2bfloat16(vl - __bfloat162float(h));
        float vr = Wr[k * 64 + n];
        __nv_bfloat16 g = __float2bfloat16(vr);
        g_wt1r[n * 128 + k] = g;
        g_wt2r[n * 128 + k] = __float2bfloat16(vr - __bfloat162float(g));
    }
}

// ---------------------------------------------------------------------------
__global__ void fill_kernel(const void* __restrict__ eiv, int n_edges) {
    const unsigned long long* q = (const unsigned long long*)eiv;
    bool is64 = (((q[0] | q[1] | q[2] | q[3]) >> 32) == 0ULL);

    int stride = gridDim.x * blockDim.x;
    for (int e = blockIdx.x * blockDim.x + threadIdx.x; e < n_edges; e += stride) {
        int s, d;
        if (is64) {
            const long long* ei = (const long long*)eiv;
            s = (int)ei[e];
            d = (int)ei[n_edges + e];
        } else {
            const int* ei = (const int*)eiv;
            s = ei[e];
            d = ei[n_edges + e];
        }
        int slot = atomicAdd(&g_cnt[d], 1);
        if (slot < BUCKET)
            g_src[(size_t)d * BUCKET + slot] = s;
    }
}

// ---------------------------------------------------------------------------
// HMMA GEMM: one 64x64 tile per CTA, 4 warps (16 rows each), 3 CTAs/SM.
// D = A1@W1 + A1@W2 + A2@W1 (2-term bf16 split, fp32 accumulate), fused k-loop.
#define ASTR 136
__global__ __launch_bounds__(128, 3) void gemm_mma_kernel(const float* __restrict__ x) {
    extern __shared__ __align__(16) char smem_raw[];
    __nv_bfloat16* A1 = (__nv_bfloat16*)smem_raw;            // 64 x 136
    __nv_bfloat16* A2 = A1 + 64 * ASTR;
    __nv_bfloat16* B1 = A2 + 64 * ASTR;                      // 64 x 136
    __nv_bfloat16* B2 = B1 + 64 * ASTR;

    int tid = threadIdx.x, warp = tid >> 5, lane = tid & 31;

    int b = blockIdx.x;
    bool is_y;
    int row0, M;
    const __nv_bfloat16 *wt1, *wt2;
    if (b < TILES_Y) { row0 = b << 6;             M = N_SRC; wt1 = g_wt1l; wt2 = g_wt2l; is_y = true;  }
    else             { row0 = (b - TILES_Y) << 6; M = N_DST; wt1 = g_wt1r; wt2 = g_wt2r; is_y = false; }

    // Load x tile (64x128 fp32), split to bf16 hi/lo with packed cvt
    #pragma unroll
    for (int i = tid; i < 64 * 32; i += 128) {
        int row = i >> 5, c4 = (i & 31) << 2;
        float4 v = make_float4(0.f, 0.f, 0.f, 0.f);
        if (row0 + row < M)
            v = *(const float4*)(x + (size_t)(row0 + row) * D_IN + c4);
        uint32_t hx = cvt_bf16x2(v.x, v.y);
        uint32_t hy = cvt_bf16x2(v.z, v.w);
        float fx0 = __uint_as_float(hx << 16);
        float fx1 = __uint_as_float(hx & 0xFFFF0000u);
        float fy0 = __uint_as_float(hy << 16);
        float fy1 = __uint_as_float(hy & 0xFFFF0000u);
        uint32_t lx = cvt_bf16x2(v.x - fx0, v.y - fx1);
        uint32_t ly = cvt_bf16x2(v.z - fy0, v.w - fy1);
        int idx = row * ASTR + c4;
        *(uint2*)(A1 + idx) = make_uint2(hx, hy);
        *(uint2*)(A2 + idx) = make_uint2(lx, ly);
    }
    // Load W^T hi/lo (64 rows x 128 k)
    #pragma unroll
    for (int i = tid; i < 64 * 16; i += 128) {
        int n = i >> 4, k8 = (i & 15) << 3;
        int idx = n * ASTR + k8;
        *(uint4*)(B1 + idx) = *(const uint4*)(wt1 + n * 128 + k8);
        *(uint4*)(B2 + idx) = *(const uint4*)(wt2 + n * 128 + k8);
    }
    __syncthreads();

    int m0 = warp << 4;
    float c[8][4];
    #pragma unroll
    for (int n = 0; n < 8; n++)
        #pragma unroll
        for (int j = 0; j < 4; j++) c[n][j] = 0.f;

    uint32_t a1b = smem_u32(A1), a2b = smem_u32(A2);
    uint32_t b1b = smem_u32(B1), b2b = smem_u32(B2);
    uint32_t aoff = (((m0 + (lane & 15)) * ASTR + ((lane >> 4) << 3)) << 1);
    uint32_t boff = (((((lane >> 4) << 3) + (lane & 7)) * ASTR + (((lane >> 3) & 1) << 3)) << 1);

    #pragma unroll 2
    for (int k = 0; k < 8; k++) {
        uint32_t ka = (k << 5);
        uint32_t x0, x1, x2, x3, y0, y1, y2, y3;
        asm volatile("ldmatrix.sync.aligned.m8n8.x4.shared.b16 {%0,%1,%2,%3}, [%4];"
                     : "=r"(x0), "=r"(x1), "=r"(x2), "=r"(x3)
                     : "r"(a1b + aoff + ka));
        asm volatile("ldmatrix.sync.aligned.m8n8.x4.shared.b16 {%0,%1,%2,%3}, [%4];"
                     : "=r"(y0), "=r"(y1), "=r"(y2), "=r"(y3)
                     : "r"(a2b + aoff + ka));
        #pragma unroll
        for (int p = 0; p < 4; p++) {
            uint32_t po = ((p * ASTR) << 5) + ka;
            uint32_t u0, u1, u2, u3, w0, w1, w2, w3;
            asm volatile("ldmatrix.sync.aligned.m8n8.x4.shared.b16 {%0,%1,%2,%3}, [%4];"
                         : "=r"(u0), "=r"(u1), "=r"(u2), "=r"(u3)
                         : "r"(b1b + boff + po));
            asm volatile("ldmatrix.sync.aligned.m8n8.x4.shared.b16 {%0,%1,%2,%3}, [%4];"
                         : "=r"(w0), "=r"(w1), "=r"(w2), "=r"(w3)
                         : "r"(b2b + boff + po));
            int n = p << 1;
            #define MMA(CN, AA0, AA1, AA2, AA3, B0, B1v)                        \
                asm volatile(                                                   \
                    "mma.sync.aligned.m16n8k16.row.col.f32.bf16.bf16.f32 "      \
                    "{%0,%1,%2,%3}, {%4,%5,%6,%7}, {%8,%9}, {%0,%1,%2,%3};"     \
                    : "+f"(c[CN][0]), "+f"(c[CN][1]), "+f"(c[CN][2]), "+f"(c[CN][3]) \
                    : "r"(AA0), "r"(AA1), "r"(AA2), "r"(AA3), "r"(B0), "r"(B1v))
            MMA(n,     x0, x1, x2, x3, u0, u1);  // A1*B1
            MMA(n + 1, x0, x1, x2, x3, u2, u3);
            MMA(n,     x0, x1, x2, x3, w0, w1);  // A1*B2
            MMA(n + 1, x0, x1, x2, x3, w2, w3);
            MMA(n,     y0, y1, y2, y3, u0, u1);  // A2*B1
            MMA(n + 1, y0, y1, y2, y3, u2, u3);
            #undef MMA
        }
    }

    // Epilogue: c fragment (row gr=lane/4 [+8], cols n*8 + 2*(lane%4) +{0,1})
    int gr = lane >> 2, gc = (lane & 3) << 1;
    int r0 = row0 + m0 + gr;
    int r1 = r0 + 8;
    if (is_y) {
        #pragma unroll
        for (int n = 0; n < 8; n++) {
            int col = (n << 3) + gc;
            if (r0 < M)
                *(__half2*)(g_yh + (size_t)r0 * D_OUT + col) =
                    __floats2half2_rn(c[n][0], c[n][1]);
            if (r1 < M)
                *(__half2*)(g_yh + (size_t)r1 * D_OUT + col) =
                    __floats2half2_rn(c[n][2], c[n][3]);
        }
    } else {
        #pragma unroll
        for (int n = 0; n < 8; n++) {
            int col = (n << 3) + gc;
            if (r0 < M)
                *(float2*)(g_z + (size_t)r0 * D_OUT + col) = make_float2(c[n][0], c[n][1]);
            if (r1 < M)
                *(float2*)(g_z + (size_t)r1 * D_OUT + col) = make_float2(c[n][2], c[n][3]);
        }
    }
}
#define SM_TOTAL (4 * 64 * ASTR * 2)

// ---------------------------------------------------------------------------
// Gather + finalize: one warp per dst row. lane = sub*8 + l (sub in [0,4),
// l in [0,8)). Lane loads uint4 (16 B = 8 halves, cols 8l..8l+7) of edge
// g + 4j + sub for j in [0,8) -> 32 edges in flight per warp per iteration.
// In-flight rows reduced with a depth-3 __hadd2 tree (fp16), one convert +
// packed f32x2 add per component per iteration.
__global__ __launch_bounds__(256) void gather_finalize_kernel(
        float* __restrict__ out, const float* __restrict__ b_l) {
    int warp = (blockIdx.x * blockDim.x + threadIdx.x) >> 5;
    int lane = threadIdx.x & 31;
    if (warp >= N_DST) return;

    int cnt = g_cnt[warp];
    int n = cnt < BUCKET ? cnt : BUCKET;
    const int* bucket = g_src + (size_t)warp * BUCKET;
    int sub = lane >> 3, l = lane & 7;
    const uint4* yh4 = (const uint4*)g_yh;    // row r -> yh4[r*8 + l]

    unsigned long long acc[4] = {0ULL, 0ULL, 0ULL, 0ULL};  // packed float2

    for (int g = 0; g < n; g += 32) {
        int idx[8];
        #pragma unroll
        for (int j = 0; j < 8; j++) {
            int e = g + (j << 2) + sub;
            idx[j] = bucket[e < n ? e : n - 1];
        }
        uint4 u[8];
        #pragma unroll
        for (int j = 0; j < 8; j++) u[j] = yh4[((size_t)idx[j] << 3) + l];
        #pragma unroll
        for (int j = 0; j < 8; j++)
            if (g + (j << 2) + sub >= n) u[j] = make_uint4(0u, 0u, 0u, 0u);

        #pragma unroll
        for (int c = 0; c < 4; c++) {
            __half2 c0 = *((__half2*)&u[0] + c), c1 = *((__half2*)&u[1] + c);
            __half2 c2 = *((__half2*)&u[2] + c), c3 = *((__half2*)&u[3] + c);
            __half2 c4 = *((__half2*)&u[4] + c), c5 = *((__half2*)&u[5] + c);
            __half2 c6 = *((__half2*)&u[6] + c), c7 = *((__half2*)&u[7] + c);
            __half2 t = __hadd2(__hadd2(__hadd2(c0, c1), __hadd2(c2, c3)),
                                __hadd2(__hadd2(c4, c5), __hadd2(c6, c7)));
            float2 f = __half22float2(t);
            unsigned long long fp;
            asm("mov.b64 %0, {%1, %2};" : "=l"(fp) : "f"(f.x), "f"(f.y));
            asm("add.rn.f32x2 %0, %0, %1;" : "+l"(acc[c]) : "l"(fp));
        }
    }

    // reduce across the 4 sub-groups (lanes with equal l end up identical)
    #pragma unroll
    for (int c = 0; c < 4; c++) {
        float fx, fy;
        asm("mov.b64 {%0, %1}, %2;" : "=f"(fx), "=f"(fy) : "l"(acc[c]));
        fx += __shfl_xor_sync(0xffffffffu, fx, 8);
        fy += __shfl_xor_sync(0xffffffffu, fy, 8);
        fx += __shfl_xor_sync(0xffffffffu, fx, 16);
        fy += __shfl_xor_sync(0xffffffffu, fy, 16);
        asm("mov.b64 %0, {%1, %2};" : "=l"(acc[c]) : "f"(fx), "f"(fy));
    }

    float inv = 1.0f / fmaxf((float)cnt, 1.0f);
    const float* zp = g_z + (size_t)warp * D_OUT + (l << 3);
    float4 z0 = *(const float4*)zp;
    float4 z1 = *(const float4*)(zp + 4);
    float4 b0 = *(const float4*)(b_l + (l << 3));
    float4 b1 = *(const float4*)(b_l + (l << 3) + 4);

    float a[8];
    #pragma unroll
    for (int c = 0; c < 4; c++)
        asm("mov.b64 {%0, %1}, %2;" : "=f"(a[2 * c]), "=f"(a[2 * c + 1]) : "l"(acc[c]));

    float v0 = a[0] * inv + b0.x + z0.x;
    float v1 = a[1] * inv + b0.y + z0.y;
    float v2 = a[2] * inv + b0.z + z0.z;
    float v3 = a[3] * inv + b0.w + z0.w;
    float v4 = a[4] * inv + b1.x + z1.x;
    float v5 = a[5] * inv + b1.y + z1.y;
    float v6 = a[6] * inv + b1.z + z1.z;
    float v7 = a[7] * inv + b1.w + z1.w;

    float m = fmaxf(fmaxf(fmaxf(v0, v1), fmaxf(v2, v3)),
                    fmaxf(fmaxf(v4, v5), fmaxf(v6, v7)));
    #pragma unroll
    for (int o = 4; o; o >>= 1) m = fmaxf(m, __shfl_xor_sync(0xffffffffu, m, o));

    float s = __expf(v0 - m) + __expf(v1 - m) + __expf(v2 - m) + __expf(v3 - m)
            + __expf(v4 - m) + __expf(v5 - m) + __expf(v6 - m) + __expf(v7 - m);
    #pragma unroll
    for (int o = 4; o; o >>= 1) s += __shfl_xor_sync(0xffffffffu, s, o);

    float lz = m + __logf(s);
    if (sub == 0) {
        float* op = out + (size_t)warp * D_OUT + (l << 3);
        *(float4*)op       = make_float4(v0 - lz, v1 - lz, v2 - lz, v3 - lz);
        *(float4*)(op + 4) = make_float4(v4 - lz, v5 - lz, v6 - lz, v7 - lz);
    }
}

// ---------------------------------------------------------------------------
extern "C" void kernel_launch(void* const* d_in, const int* in_sizes, int n_in,
                              void* d_out, int out_size) {
    const float* x  = (const float*)d_in[0];
    const float* Wl = (const float*)d_in[1];
    const float* bl = (const float*)d_in[2];
    const float* Wr = (const float*)d_in[3];
    const void*  ei = d_in[4];
    int n_edges = in_sizes[4] / 2;
    float* out = (float*)d_out;

    prep_kernel<<<(N_DST + 255) / 256, 256>>>(Wl, Wr);
    fill_kernel<<<2048, 256>>>(ei, n_edges);

    cudaFuncSetAttribute(gemm_mma_kernel,
                         cudaFuncAttributeMaxDynamicSharedMemorySize, SM_TOTAL);
    gemm_mma_kernel<<<TILES_Y + TILES_Z, 128, SM_TOTAL>>>(x);

    gather_finalize_kernel<<<(N_DST * 32 + 255) / 256, 256>>>(out, bl);
}

// round 10
// speedup vs baseline: 1.1919x; 1.1919x over previous
#include <cuda_runtime.h>
#include <cuda_fp16.h>
#include <cuda_bf16.h>
#include <math.h>
#include <stdint.h>

#define N_SRC 100000
#define N_DST 50000
#define D_IN  128
#define D_OUT 64
#define BUCKET 128

#define TILES_Y 1563           // ceil(100000/64)
#define TILES_Z 782            // ceil(50000/64)

// ---------------- scratch (device globals; no allocations allowed) ---------
__device__ __half g_yh[(size_t)N_SRC * D_OUT];     // fp16(x @ W_l)   12.8 MB
__device__ float  g_z[(size_t)N_DST * D_OUT];      // x[:N_DST]@W_r   12.8 MB
__device__ int    g_cnt[N_DST];
__device__ int    g_src[(size_t)N_DST * BUCKET];   // bucketed CSR    25.6 MB
// W^T split into bf16 hi/lo, [n][k] row-major
__device__ __nv_bfloat16 g_wt1l[64 * 128], g_wt2l[64 * 128];
__device__ __nv_bfloat16 g_wt1r[64 * 128], g_wt2r[64 * 128];

__device__ __forceinline__ uint32_t smem_u32(const void* p) {
    uint32_t a;
    asm("{ .reg .u64 t; cvta.to.shared.u64 t, %1; cvt.u32.u64 %0, t; }"
        : "=r"(a) : "l"(p));
    return a;
}

// ---------------------------------------------------------------------------
// W^T bf16 hi/lo split (wt[n][k] = W[k][n]).
// NOTE: does NOT touch g_cnt — the forked stream owns g_cnt/g_src until the
// join event (the R9 failure was prep re-zeroing counters mid-fill).
__global__ void prep_kernel(const float* __restrict__ Wl,
                            const float* __restrict__ Wr) {
    int i = blockIdx.x * blockDim.x + threadIdx.x;
    if (i < 64 * 128) {
        int n = i & 63, k = i >> 6;
        float vl = Wl[k * 64 + n];
        __nv_bfloat16 h = __float2bfloat16(vl);
        g_wt1l[n * 128 + k] = h;
        g_wt2l[n * 128 + k] = __float2bfloat16(vl - __bfloat162float(h));
        float vr = Wr[k * 64 + n];
        __nv_bfloat16 g = __float2bfloat16(vr);
        g_wt1r[n * 128 + k] = g;
        g_wt2r[n * 128 + k] = __float2bfloat16(vr - __bfloat162float(g));
    }
}

// ---------------------------------------------------------------------------
__global__ void zero_cnt_kernel() {
    int i = blockIdx.x * blockDim.x + threadIdx.x;
    if (i < N_DST) g_cnt[i] = 0;
}

__global__ void fill_kernel(const void* __restrict__ eiv, int n_edges) {
    const unsigned long long* q = (const unsigned long long*)eiv;
    bool is64 = (((q[0] | q[1] | q[2] | q[3]) >> 32) == 0ULL);

    int stride = gridDim.x * blockDim.x;
    for (int e = blockIdx.x * blockDim.x + threadIdx.x; e < n_edges; e += stride) {
        int s, d;
        if (is64) {
            const long long* ei = (const long long*)eiv;
            s = (int)ei[e];
            d = (int)ei[n_edges + e];
        } else {
            const int* ei = (const int*)eiv;
            s = ei[e];
            d = ei[n_edges + e];
        }
        int slot = atomicAdd(&g_cnt[d], 1);
        if (slot < BUCKET)
            g_src[(size_t)d * BUCKET + slot] = s;
    }
}

// ---------------------------------------------------------------------------
// HMMA GEMM: one 64x64 tile per CTA, 4 warps (16 rows each), 3 CTAs/SM.
// D = A1@W1 + A1@W2 + A2@W1 (2-term bf16 split, fp32 accumulate), fused k-loop.
#define ASTR 136
__global__ __launch_bounds__(128, 3) void gemm_mma_kernel(const float* __restrict__ x) {
    extern __shared__ __align__(16) char smem_raw[];
    __nv_bfloat16* A1 = (__nv_bfloat16*)smem_raw;            // 64 x 136
    __nv_bfloat16* A2 = A1 + 64 * ASTR;
    __nv_bfloat16* B1 = A2 + 64 * ASTR;                      // 64 x 136
    __nv_bfloat16* B2 = B1 + 64 * ASTR;

    int tid = threadIdx.x, warp = tid >> 5, lane = tid & 31;

    int b = blockIdx.x;
    bool is_y;
    int row0, M;
    const __nv_bfloat16 *wt1, *wt2;
    if (b < TILES_Y) { row0 = b << 6;             M = N_SRC; wt1 = g_wt1l; wt2 = g_wt2l; is_y = true;  }
    else             { row0 = (b - TILES_Y) << 6; M = N_DST; wt1 = g_wt1r; wt2 = g_wt2r; is_y = false; }

    // Load x tile (64x128 fp32), split to bf16 hi/lo
    #pragma unroll
    for (int i = tid; i < 64 * 32; i += 128) {
        int row = i >> 5, c4 = (i & 31) << 2;
        float4 v = make_float4(0.f, 0.f, 0.f, 0.f);
        if (row0 + row < M)
            v = *(const float4*)(x + (size_t)(row0 + row) * D_IN + c4);
        __nv_bfloat16 h0 = __float2bfloat16(v.x), h1 = __float2bfloat16(v.y);
        __nv_bfloat16 h2 = __float2bfloat16(v.z), h3 = __float2bfloat16(v.w);
        __nv_bfloat16 r0 = __float2bfloat16(v.x - __bfloat162float(h0));
        __nv_bfloat16 r1 = __float2bfloat16(v.y - __bfloat162float(h1));
        __nv_bfloat16 r2 = __float2bfloat16(v.z - __bfloat162float(h2));
        __nv_bfloat16 r3 = __float2bfloat16(v.w - __bfloat162float(h3));
        int idx = row * ASTR + c4;
        uint2 hi, lo;
        hi.x = (uint32_t)__bfloat16_as_ushort(h0) | ((uint32_t)__bfloat16_as_ushort(h1) << 16);
        hi.y = (uint32_t)__bfloat16_as_ushort(h2) | ((uint32_t)__bfloat16_as_ushort(h3) << 16);
        lo.x = (uint32_t)__bfloat16_as_ushort(r0) | ((uint32_t)__bfloat16_as_ushort(r1) << 16);
        lo.y = (uint32_t)__bfloat16_as_ushort(r2) | ((uint32_t)__bfloat16_as_ushort(r3) << 16);
        *(uint2*)(A1 + idx) = hi;
        *(uint2*)(A2 + idx) = lo;
    }
    // Load W^T hi/lo (64 rows x 128 k)
    #pragma unroll
    for (int i = tid; i < 64 * 16; i += 128) {
        int n = i >> 4, k8 = (i & 15) << 3;
        int idx = n * ASTR + k8;
        *(uint4*)(B1 + idx) = *(const uint4*)(wt1 + n * 128 + k8);
        *(uint4*)(B2 + idx) = *(const uint4*)(wt2 + n * 128 + k8);
    }
    __syncthreads();

    int m0 = warp << 4;
    float c[8][4];
    #pragma unroll
    for (int n = 0; n < 8; n++)
        #pragma unroll
        for (int j = 0; j < 4; j++) c[n][j] = 0.f;

    uint32_t a1b = smem_u32(A1), a2b = smem_u32(A2);
    uint32_t b1b = smem_u32(B1), b2b = smem_u32(B2);
    uint32_t aoff = (((m0 + (lane & 15)) * ASTR + ((lane >> 4) << 3)) << 1);
    uint32_t boff = (((((lane >> 4) << 3) + (lane & 7)) * ASTR + (((lane >> 3) & 1) << 3)) << 1);

    #pragma unroll 2
    for (int k = 0; k < 8; k++) {
        uint32_t ka = (k << 5);
        uint32_t x0, x1, x2, x3, y0, y1, y2, y3;
        asm volatile("ldmatrix.sync.aligned.m8n8.x4.shared.b16 {%0,%1,%2,%3}, [%4];"
                     : "=r"(x0), "=r"(x1), "=r"(x2), "=r"(x3)
                     : "r"(a1b + aoff + ka));
        asm volatile("ldmatrix.sync.aligned.m8n8.x4.shared.b16 {%0,%1,%2,%3}, [%4];"
                     : "=r"(y0), "=r"(y1), "=r"(y2), "=r"(y3)
                     : "r"(a2b + aoff + ka));
        #pragma unroll
        for (int p = 0; p < 4; p++) {
            uint32_t po = ((p * ASTR) << 5) + ka;
            uint32_t u0, u1, u2, u3, w0, w1, w2, w3;
            asm volatile("ldmatrix.sync.aligned.m8n8.x4.shared.b16 {%0,%1,%2,%3}, [%4];"
                         : "=r"(u0), "=r"(u1), "=r"(u2), "=r"(u3)
                         : "r"(b1b + boff + po));
            asm volatile("ldmatrix.sync.aligned.m8n8.x4.shared.b16 {%0,%1,%2,%3}, [%4];"
                         : "=r"(w0), "=r"(w1), "=r"(w2), "=r"(w3)
                         : "r"(b2b + boff + po));
            int n = p << 1;
            #define MMA(CN, AA0, AA1, AA2, AA3, B0, B1v)                        \
                asm volatile(                                                   \
                    "mma.sync.aligned.m16n8k16.row.col.f32.bf16.bf16.f32 "      \
                    "{%0,%1,%2,%3}, {%4,%5,%6,%7}, {%8,%9}, {%0,%1,%2,%3};"     \
                    : "+f"(c[CN][0]), "+f"(c[CN][1]), "+f"(c[CN][2]), "+f"(c[CN][3]) \
                    : "r"(AA0), "r"(AA1), "r"(AA2), "r"(AA3), "r"(B0), "r"(B1v))
            MMA(n,     x0, x1, x2, x3, u0, u1);  // A1*B1
            MMA(n + 1, x0, x1, x2, x3, u2, u3);
            MMA(n,     x0, x1, x2, x3, w0, w1);  // A1*B2
            MMA(n + 1, x0, x1, x2, x3, w2, w3);
            MMA(n,     y0, y1, y2, y3, u0, u1);  // A2*B1
            MMA(n + 1, y0, y1, y2, y3, u2, u3);
            #undef MMA
        }
    }

    // Epilogue: c fragment (row gr=lane/4 [+8], cols n*8 + 2*(lane%4) +{0,1})
    int gr = lane >> 2, gc = (lane & 3) << 1;
    int r0 = row0 + m0 + gr;
    int r1 = r0 + 8;
    if (is_y) {
        #pragma unroll
        for (int n = 0; n < 8; n++) {
            int col = (n << 3) + gc;
            if (r0 < M)
                *(__half2*)(g_yh + (size_t)r0 * D_OUT + col) =
                    __floats2half2_rn(c[n][0], c[n][1]);
            if (r1 < M)
                *(__half2*)(g_yh + (size_t)r1 * D_OUT + col) =
                    __floats2half2_rn(c[n][2], c[n][3]);
        }
    } else {
        #pragma unroll
        for (int n = 0; n < 8; n++) {
            int col = (n << 3) + gc;
            if (r0 < M)
                *(float2*)(g_z + (size_t)r0 * D_OUT + col) = make_float2(c[n][0], c[n][1]);
            if (r1 < M)
                *(float2*)(g_z + (size_t)r1 * D_OUT + col) = make_float2(c[n][2], c[n][3]);
        }
    }
}
#define SM_TOTAL (4 * 64 * ASTR * 2)

// ---------------------------------------------------------------------------
// Gather + finalize: one warp per dst row; lane owns cols {2l, 2l+1} (half2).
// 8 independent 4B gathers in flight per lane (MLP=8) with int4 index
// prefetch; in-flight values reduced by a depth-3 __hadd2 tree (7 ops) +
// one convert + one packed f32x2 add.
__global__ __launch_bounds__(256) void gather_finalize_kernel(
        float* __restrict__ out, const float* __restrict__ b_l) {
    int warp = (blockIdx.x * blockDim.x + threadIdx.x) >> 5;
    int lane = threadIdx.x & 31;
    if (warp >= N_DST) return;

    int cnt = g_cnt[warp];
    int n = cnt < BUCKET ? cnt : BUCKET;
    const int* bucket = g_src + (size_t)warp * BUCKET;
    const __half2* yh = (const __half2*)g_yh + lane;   // row r -> yh[r*32]

    unsigned long long acc = 0ULL;                     // packed float2
    if (n > 0) {
        __half2 zero = __half2half2(__ushort_as_half(0));
        int4 p0 = *(const int4*)bucket;
        int4 p1 = *(const int4*)(bucket + 4);
        for (int g = 0; g < n; g += 8) {
            int4 c0 = p0, c1 = p1;
            if (g + 8 < n) {
                p0 = *(const int4*)(bucket + g + 8);
                p1 = *(const int4*)(bucket + g + 12);
            }
            __half2 h0 = (g + 0 < n) ? yh[(size_t)c0.x << 5] : zero;
            __half2 h1 = (g + 1 < n) ? yh[(size_t)c0.y << 5] : zero;
            __half2 h2 = (g + 2 < n) ? yh[(size_t)c0.z << 5] : zero;
            __half2 h3 = (g + 3 < n) ? yh[(size_t)c0.w << 5] : zero;
            __half2 h4 = (g + 4 < n) ? yh[(size_t)c1.x << 5] : zero;
            __half2 h5 = (g + 5 < n) ? yh[(size_t)c1.y << 5] : zero;
            __half2 h6 = (g + 6 < n) ? yh[(size_t)c1.z << 5] : zero;
            __half2 h7 = (g + 7 < n) ? yh[(size_t)c1.w << 5] : zero;
            __half2 t = __hadd2(__hadd2(__hadd2(h0, h1), __hadd2(h2, h3)),
                                __hadd2(__hadd2(h4, h5), __hadd2(h6, h7)));
            float2 f = __half22float2(t);
            unsigned long long fp;
            asm("mov.b64 %0, {%1, %2};" : "=l"(fp) : "f"(f.x), "f"(f.y));
            asm("add.rn.f32x2 %0, %0, %1;" : "+l"(acc) : "l"(fp));
        }
    }

    float a0, a1;
    asm("mov.b64 {%0, %1}, %2;" : "=f"(a0), "=f"(a1) : "l"(acc));

    float inv = 1.0f / fmaxf((float)cnt, 1.0f);
    float2 zz = *(const float2*)(g_z + (size_t)warp * D_OUT + (lane << 1));
    float2 bb = *(const float2*)(b_l + (lane << 1));
    float v0 = a0 * inv + bb.x + zz.x;
    float v1 = a1 * inv + bb.y + zz.y;

    float m = fmaxf(v0, v1);
    #pragma unroll
    for (int o = 16; o; o >>= 1) m = fmaxf(m, __shfl_xor_sync(0xffffffffu, m, o));

    float s = __expf(v0 - m) + __expf(v1 - m);
    #pragma unroll
    for (int o = 16; o; o >>= 1) s += __shfl_xor_sync(0xffffffffu, s, o);

    float lz = m + __logf(s);
    *(float2*)(out + (size_t)warp * D_OUT + (lane << 1)) =
        make_float2(v0 - lz, v1 - lz);
}

// ---------------------------------------------------------------------------
extern "C" void kernel_launch(void* const* d_in, const int* in_sizes, int n_in,
                              void* d_out, int out_size) {
    const float* x  = (const float*)d_in[0];
    const float* Wl = (const float*)d_in[1];
    const float* bl = (const float*)d_in[2];
    const float* Wr = (const float*)d_in[3];
    const void*  ei = d_in[4];
    int n_edges = in_sizes[4] / 2;
    float* out = (float*)d_out;

    // One-time resources for the forked-stream graph topology (no device mem).
    static cudaStream_t side = nullptr;
    static cudaEvent_t ev_fork = nullptr, ev_join = nullptr;
    if (side == nullptr) {
        cudaStreamCreateWithFlags(&side, cudaStreamNonBlocking);
        cudaEventCreateWithFlags(&ev_fork, cudaEventDisableTiming);
        cudaEventCreateWithFlags(&ev_join, cudaEventDisableTiming);
    }

    // Fork: CSR build (zero + fill) runs concurrently with prep + GEMM.
    // The side stream has EXCLUSIVE ownership of g_cnt/g_src until ev_join.
    cudaEventRecord(ev_fork, 0);
    cudaStreamWaitEvent(side, ev_fork, 0);
    zero_cnt_kernel<<<(N_DST + 255) / 256, 256, 0, side>>>();
    fill_kernel<<<2048, 256, 0, side>>>(ei, n_edges);
    cudaEventRecord(ev_join, side);

    // Main stream: W split, then tensor-core projections.
    prep_kernel<<<32, 256>>>(Wl, Wr);
    cudaFuncSetAttribute(gemm_mma_kernel,
                         cudaFuncAttributeMaxDynamicSharedMemorySize, SM_TOTAL);
    gemm_mma_kernel<<<TILES_Y + TILES_Z, 128, SM_TOTAL>>>(x);

    // Join, then gather + finalize.
    cudaStreamWaitEvent(0, ev_join, 0);
    gather_finalize_kernel<<<(N_DST * 32 + 255) / 256, 256>>>(out, bl);
}